// round 1
// baseline (speedup 1.0000x reference)
#include <cuda_runtime.h>
#include <cstdint>

typedef unsigned long long u64;

// ---------- packed f32x2 primitives (Blackwell sm_103a) ----------
__device__ __forceinline__ u64 fma2(u64 a, u64 b, u64 c) {
    u64 d;
    asm("fma.rn.f32x2 %0, %1, %2, %3;" : "=l"(d) : "l"(a), "l"(b), "l"(c));
    return d;
}
__device__ __forceinline__ u64 mul2(u64 a, u64 b) {
    u64 d;
    asm("mul.rn.f32x2 %0, %1, %2;" : "=l"(d) : "l"(a), "l"(b));
    return d;
}
__device__ __forceinline__ u64 pk(float lo, float hi) {
    u64 r;
    asm("mov.b64 %0, {%1, %2};" : "=l"(r) : "f"(lo), "f"(hi));
    return r;
}
__device__ __forceinline__ void upk(u64 v, float& lo, float& hi) {
    asm("mov.b64 {%0, %1}, %2;" : "=f"(lo), "=f"(hi) : "l"(v));
}
__device__ __forceinline__ u64 dup2(float w) { return pk(w, w); }

// ---------- fast-but-accurate activations (ex2 + rcp, ~1e-6 rel err) ----------
__device__ __forceinline__ float sig_(float x) {
    float e;
    asm("ex2.approx.f32 %0, %1;" : "=f"(e) : "f"(x * -1.4426950408889634f));
    float r;
    asm("rcp.approx.f32 %0, %1;" : "=f"(r) : "f"(e + 1.0f));
    return r;
}
__device__ __forceinline__ float tanh_(float x) {
    // tanh(x) = 2*sigmoid(2x) - 1
    return fmaf(2.0f, sig_(2.0f * x), -1.0f);
}
__device__ __forceinline__ u64 sig2(u64 z) {
    float l, h; upk(z, l, h);
    return pk(sig_(l), sig_(h));
}
__device__ __forceinline__ u64 tanh2(u64 z) {
    float l, h; upk(z, l, h);
    return pk(tanh_(l), tanh_(h));
}

#define TT 14
#define HH 7
#define FF 12
#define NTHR 128

__global__ __launch_bounds__(NTHR)
void lstm_fused_kernel(
    const float* __restrict__ x,
    const float* __restrict__ w1,  const float* __restrict__ b1,
    const float* __restrict__ wih0, const float* __restrict__ whh0,
    const float* __restrict__ bih0, const float* __restrict__ bhh0,
    const float* __restrict__ wih1, const float* __restrict__ whh1,
    const float* __restrict__ bih1, const float* __restrict__ bhh1,
    const float* __restrict__ w2,  const float* __restrict__ b2,
    float* __restrict__ out, int half)
{
    // weights duplicated as (w,w) pairs for f32x2 FMAs
    __shared__ u64 s_wih0[4 * HH];        // 28
    __shared__ u64 s_b0[4 * HH];          // 28 (b_ih0 + b_hh0)
    __shared__ u64 s_b1[4 * HH];          // 28 (b_ih1 + b_hh1)
    __shared__ u64 s_whh0[4 * HH * HH];   // 196
    __shared__ u64 s_wih1[4 * HH * HH];   // 196
    __shared__ u64 s_whh1[4 * HH * HH];   // 196
    __shared__ u64 s_w2[2 * HH];          // 14
    __shared__ float s_w1[FF];
    __shared__ float s_b1lin, s_b2;
    __shared__ u64 s_u[TT][NTHR];         // per-thread tanh(linear1) values

    const int tid = threadIdx.x;

    for (int i = tid; i < 4 * HH; i += NTHR) {
        s_wih0[i] = dup2(wih0[i]);
        s_b0[i]   = dup2(bih0[i] + bhh0[i]);
        s_b1[i]   = dup2(bih1[i] + bhh1[i]);
    }
    for (int i = tid; i < 4 * HH * HH; i += NTHR) {
        s_whh0[i] = dup2(whh0[i]);
        s_wih1[i] = dup2(wih1[i]);
        s_whh1[i] = dup2(whh1[i]);
    }
    if (tid < 2 * HH) s_w2[tid] = dup2(w2[tid]);
    if (tid < FF)     s_w1[tid] = w1[tid];
    if (tid == 0) { s_b1lin = b1[0]; s_b2 = b2[0]; }
    __syncthreads();

    const int g  = blockIdx.x * NTHR + tid;
    if (g >= half) return;
    const int b0 = g;
    const int bb1 = g + half;

    // ---- phase 1: u[t] = tanh(x[b,t,:] . w1 + b1) for both packed elements ----
    float w1r[FF];
#pragma unroll
    for (int f = 0; f < FF; f++) w1r[f] = s_w1[f];
    const float blin = s_b1lin;

#pragma unroll 1
    for (int t = 0; t < TT; t++) {
        const float4* p0 = (const float4*)(x + ((long)b0 * TT + t) * FF);
        const float4* p1 = (const float4*)(x + ((long)bb1 * TT + t) * FF);
        float4 a0 = p0[0], a1 = p0[1], a2 = p0[2];
        float4 c0v = p1[0], c1v = p1[1], c2v = p1[2];
        float s0 = blin, s1 = blin;
        s0 = fmaf(a0.x, w1r[0], s0);  s0 = fmaf(a0.y, w1r[1], s0);
        s0 = fmaf(a0.z, w1r[2], s0);  s0 = fmaf(a0.w, w1r[3], s0);
        s0 = fmaf(a1.x, w1r[4], s0);  s0 = fmaf(a1.y, w1r[5], s0);
        s0 = fmaf(a1.z, w1r[6], s0);  s0 = fmaf(a1.w, w1r[7], s0);
        s0 = fmaf(a2.x, w1r[8], s0);  s0 = fmaf(a2.y, w1r[9], s0);
        s0 = fmaf(a2.z, w1r[10], s0); s0 = fmaf(a2.w, w1r[11], s0);
        s1 = fmaf(c0v.x, w1r[0], s1);  s1 = fmaf(c0v.y, w1r[1], s1);
        s1 = fmaf(c0v.z, w1r[2], s1);  s1 = fmaf(c0v.w, w1r[3], s1);
        s1 = fmaf(c1v.x, w1r[4], s1);  s1 = fmaf(c1v.y, w1r[5], s1);
        s1 = fmaf(c1v.z, w1r[6], s1);  s1 = fmaf(c1v.w, w1r[7], s1);
        s1 = fmaf(c2v.x, w1r[8], s1);  s1 = fmaf(c2v.y, w1r[9], s1);
        s1 = fmaf(c2v.z, w1r[10], s1); s1 = fmaf(c2v.w, w1r[11], s1);
        s_u[t][tid] = pk(tanh_(s0), tanh_(s1));
    }

    // ---- phase 2: two stacked LSTM layers, interleaved per time step ----
    u64 h0[HH], c0[HH], h1[HH], c1[HH];
#pragma unroll
    for (int j = 0; j < HH; j++) { h0[j] = 0ull; c0[j] = 0ull; h1[j] = 0ull; c1[j] = 0ull; }

#pragma unroll 1
    for (int t = 0; t < TT; t++) {
        const u64 xin = s_u[t][tid];

        // layer 0 (scalar input)
        u64 hn[HH];
#pragma unroll
        for (int j = 0; j < HH; j++) {
            u64 zi = fma2(xin, s_wih0[j],          s_b0[j]);
            u64 zf = fma2(xin, s_wih0[HH + j],     s_b0[HH + j]);
            u64 zg = fma2(xin, s_wih0[2 * HH + j], s_b0[2 * HH + j]);
            u64 zo = fma2(xin, s_wih0[3 * HH + j], s_b0[3 * HH + j]);
#pragma unroll
            for (int k = 0; k < HH; k++) {
                zi = fma2(h0[k], s_whh0[j * HH + k],            zi);
                zf = fma2(h0[k], s_whh0[(HH + j) * HH + k],     zf);
                zg = fma2(h0[k], s_whh0[(2 * HH + j) * HH + k], zg);
                zo = fma2(h0[k], s_whh0[(3 * HH + j) * HH + k], zo);
            }
            u64 cv = fma2(sig2(zf), c0[j], mul2(sig2(zi), tanh2(zg)));
            c0[j] = cv;
            hn[j] = mul2(sig2(zo), tanh2(cv));
        }

        // layer 1 (input = layer-0 hidden just computed)
        u64 hn1[HH];
#pragma unroll
        for (int j = 0; j < HH; j++) {
            u64 zi = s_b1[j];
            u64 zf = s_b1[HH + j];
            u64 zg = s_b1[2 * HH + j];
            u64 zo = s_b1[3 * HH + j];
#pragma unroll
            for (int k = 0; k < HH; k++) {
                zi = fma2(hn[k], s_wih1[j * HH + k],            zi);
                zf = fma2(hn[k], s_wih1[(HH + j) * HH + k],     zf);
                zg = fma2(hn[k], s_wih1[(2 * HH + j) * HH + k], zg);
                zo = fma2(hn[k], s_wih1[(3 * HH + j) * HH + k], zo);
            }
#pragma unroll
            for (int k = 0; k < HH; k++) {
                zi = fma2(h1[k], s_whh1[j * HH + k],            zi);
                zf = fma2(h1[k], s_whh1[(HH + j) * HH + k],     zf);
                zg = fma2(h1[k], s_whh1[(2 * HH + j) * HH + k], zg);
                zo = fma2(h1[k], s_whh1[(3 * HH + j) * HH + k], zo);
            }
            u64 cv = fma2(sig2(zf), c1[j], mul2(sig2(zi), tanh2(zg)));
            c1[j] = cv;
            hn1[j] = mul2(sig2(zo), tanh2(cv));
        }

#pragma unroll
        for (int j = 0; j < HH; j++) { h0[j] = hn[j]; h1[j] = hn1[j]; }
    }

    // ---- phase 3: out = [h0_final, h1_final] . w2 + b2 ----
    u64 acc = pk(s_b2, s_b2);
#pragma unroll
    for (int j = 0; j < HH; j++) {
        acc = fma2(h0[j], s_w2[j], acc);
        acc = fma2(h1[j], s_w2[HH + j], acc);
    }
    float olo, ohi;
    upk(acc, olo, ohi);
    out[b0]  = olo;
    out[bb1] = ohi;
}

extern "C" void kernel_launch(void* const* d_in, const int* in_sizes, int n_in,
                              void* d_out, int out_size) {
    const float* x    = (const float*)d_in[0];
    const float* w1   = (const float*)d_in[1];
    const float* b1   = (const float*)d_in[2];
    const float* wih0 = (const float*)d_in[3];
    const float* whh0 = (const float*)d_in[4];
    const float* bih0 = (const float*)d_in[5];
    const float* bhh0 = (const float*)d_in[6];
    const float* wih1 = (const float*)d_in[7];
    const float* whh1 = (const float*)d_in[8];
    const float* bih1 = (const float*)d_in[9];
    const float* bhh1 = (const float*)d_in[10];
    const float* w2   = (const float*)d_in[11];
    const float* b2   = (const float*)d_in[12];
    float* out = (float*)d_out;

    const int B    = out_size;       // 262144
    const int half = B / 2;          // each thread packs 2 batch elements (f32x2)
    const int grid = (half + NTHR - 1) / NTHR;

    lstm_fused_kernel<<<grid, NTHR>>>(x, w1, b1, wih0, whh0, bih0, bhh0,
                                      wih1, whh1, bih1, bhh1, w2, b2,
                                      out, half);
}

// round 2
// speedup vs baseline: 2.2524x; 2.2524x over previous
#include <cuda_runtime.h>
#include <cstdint>

// ---------- fast-but-accurate activations (ex2 + rcp, ~1e-6 rel err) ----------
__device__ __forceinline__ float sig_(float x) {
    float e;
    asm("ex2.approx.f32 %0, %1;" : "=f"(e) : "f"(x * -1.4426950408889634f));
    float r;
    asm("rcp.approx.f32 %0, %1;" : "=f"(r) : "f"(e + 1.0f));
    return r;
}
__device__ __forceinline__ float tanh_(float x) {
    // tanh(x) = 2*sigmoid(2x) - 1
    return fmaf(2.0f, sig_(2.0f * x), -1.0f);
}

#define TT 14
#define HH 7
#define FF 12
#define NTHR 128

__global__ __launch_bounds__(NTHR)
void lstm_fused_kernel(
    const float* __restrict__ x,
    const float* __restrict__ w1,  const float* __restrict__ b1,
    const float* __restrict__ wih0, const float* __restrict__ whh0,
    const float* __restrict__ bih0, const float* __restrict__ bhh0,
    const float* __restrict__ wih1, const float* __restrict__ whh1,
    const float* __restrict__ bih1, const float* __restrict__ bhh1,
    const float* __restrict__ w2,  const float* __restrict__ b2,
    float* __restrict__ out, int B)
{
    __shared__ float s_wih0[4 * HH];        // 28
    __shared__ float s_b0[4 * HH];          // 28 (b_ih0 + b_hh0)
    __shared__ float s_b1[4 * HH];          // 28 (b_ih1 + b_hh1)
    __shared__ float s_whh0[4 * HH * HH];   // 196
    __shared__ float s_wih1[4 * HH * HH];   // 196
    __shared__ float s_whh1[4 * HH * HH];   // 196
    __shared__ float s_w2[2 * HH];          // 14
    __shared__ float s_w1[FF];
    __shared__ float s_b1lin, s_b2;
    __shared__ float s_u[TT][NTHR];         // per-thread tanh(linear1) values

    const int tid = threadIdx.x;

    for (int i = tid; i < 4 * HH; i += NTHR) {
        s_wih0[i] = wih0[i];
        s_b0[i]   = bih0[i] + bhh0[i];
        s_b1[i]   = bih1[i] + bhh1[i];
    }
    for (int i = tid; i < 4 * HH * HH; i += NTHR) {
        s_whh0[i] = whh0[i];
        s_wih1[i] = wih1[i];
        s_whh1[i] = whh1[i];
    }
    if (tid < 2 * HH) s_w2[tid] = w2[tid];
    if (tid < FF)     s_w1[tid] = w1[tid];
    if (tid == 0) { s_b1lin = b1[0]; s_b2 = b2[0]; }
    __syncthreads();

    const int b = blockIdx.x * NTHR + tid;
    if (b >= B) return;

    // ---- phase 1: u[t] = tanh(x[b,t,:] . w1 + b1) ----
    {
        const float blin = s_b1lin;
        const float4* px = (const float4*)(x + (long)b * TT * FF);
#pragma unroll 1
        for (int t = 0; t < TT; t++) {
            float4 a0 = px[t * 3 + 0];
            float4 a1 = px[t * 3 + 1];
            float4 a2 = px[t * 3 + 2];
            float s = blin;
            s = fmaf(a0.x, s_w1[0], s);  s = fmaf(a0.y, s_w1[1], s);
            s = fmaf(a0.z, s_w1[2], s);  s = fmaf(a0.w, s_w1[3], s);
            s = fmaf(a1.x, s_w1[4], s);  s = fmaf(a1.y, s_w1[5], s);
            s = fmaf(a1.z, s_w1[6], s);  s = fmaf(a1.w, s_w1[7], s);
            s = fmaf(a2.x, s_w1[8], s);  s = fmaf(a2.y, s_w1[9], s);
            s = fmaf(a2.z, s_w1[10], s); s = fmaf(a2.w, s_w1[11], s);
            s_u[t][tid] = tanh_(s);
        }
    }

    // ---- phase 2: two stacked LSTM layers, interleaved per time step ----
    float h0[HH], c0[HH], h1[HH], c1[HH];
#pragma unroll
    for (int j = 0; j < HH; j++) { h0[j] = 0.f; c0[j] = 0.f; h1[j] = 0.f; c1[j] = 0.f; }

#pragma unroll 1
    for (int t = 0; t < TT; t++) {
        const float xin = s_u[t][tid];

        // layer 0 (scalar input)
        float hn[HH];
#pragma unroll
        for (int j = 0; j < HH; j++) {
            float zi = fmaf(xin, s_wih0[j],          s_b0[j]);
            float zf = fmaf(xin, s_wih0[HH + j],     s_b0[HH + j]);
            float zg = fmaf(xin, s_wih0[2 * HH + j], s_b0[2 * HH + j]);
            float zo = fmaf(xin, s_wih0[3 * HH + j], s_b0[3 * HH + j]);
#pragma unroll
            for (int k = 0; k < HH; k++) {
                zi = fmaf(h0[k], s_whh0[j * HH + k],            zi);
                zf = fmaf(h0[k], s_whh0[(HH + j) * HH + k],     zf);
                zg = fmaf(h0[k], s_whh0[(2 * HH + j) * HH + k], zg);
                zo = fmaf(h0[k], s_whh0[(3 * HH + j) * HH + k], zo);
            }
            float cv = fmaf(sig_(zf), c0[j], sig_(zi) * tanh_(zg));
            c0[j] = cv;
            hn[j] = sig_(zo) * tanh_(cv);
        }

        // layer 1 (input = layer-0 hidden just computed)
        float hn1[HH];
#pragma unroll
        for (int j = 0; j < HH; j++) {
            float zi = s_b1[j];
            float zf = s_b1[HH + j];
            float zg = s_b1[2 * HH + j];
            float zo = s_b1[3 * HH + j];
#pragma unroll
            for (int k = 0; k < HH; k++) {
                zi = fmaf(hn[k], s_wih1[j * HH + k],            zi);
                zf = fmaf(hn[k], s_wih1[(HH + j) * HH + k],     zf);
                zg = fmaf(hn[k], s_wih1[(2 * HH + j) * HH + k], zg);
                zo = fmaf(hn[k], s_wih1[(3 * HH + j) * HH + k], zo);
            }
#pragma unroll
            for (int k = 0; k < HH; k++) {
                zi = fmaf(h1[k], s_whh1[j * HH + k],            zi);
                zf = fmaf(h1[k], s_whh1[(HH + j) * HH + k],     zf);
                zg = fmaf(h1[k], s_whh1[(2 * HH + j) * HH + k], zg);
                zo = fmaf(h1[k], s_whh1[(3 * HH + j) * HH + k], zo);
            }
            float cv = fmaf(sig_(zf), c1[j], sig_(zi) * tanh_(zg));
            c1[j] = cv;
            hn1[j] = sig_(zo) * tanh_(cv);
        }

#pragma unroll
        for (int j = 0; j < HH; j++) { h0[j] = hn[j]; h1[j] = hn1[j]; }
    }

    // ---- phase 3: out = [h0_final, h1_final] . w2 + b2 ----
    float acc = s_b2;
#pragma unroll
    for (int j = 0; j < HH; j++) {
        acc = fmaf(h0[j], s_w2[j], acc);
        acc = fmaf(h1[j], s_w2[HH + j], acc);
    }
    out[b] = acc;
}

extern "C" void kernel_launch(void* const* d_in, const int* in_sizes, int n_in,
                              void* d_out, int out_size) {
    const float* x    = (const float*)d_in[0];
    const float* w1   = (const float*)d_in[1];
    const float* b1   = (const float*)d_in[2];
    const float* wih0 = (const float*)d_in[3];
    const float* whh0 = (const float*)d_in[4];
    const float* bih0 = (const float*)d_in[5];
    const float* bhh0 = (const float*)d_in[6];
    const float* wih1 = (const float*)d_in[7];
    const float* whh1 = (const float*)d_in[8];
    const float* bih1 = (const float*)d_in[9];
    const float* bhh1 = (const float*)d_in[10];
    const float* w2   = (const float*)d_in[11];
    const float* b2   = (const float*)d_in[12];
    float* out = (float*)d_out;

    const int B    = out_size;       // 262144
    const int grid = (B + NTHR - 1) / NTHR;

    lstm_fused_kernel<<<grid, NTHR>>>(x, w1, b1, wih0, whh0, bih0, bhh0,
                                      wih1, whh1, bih1, bhh1, w2, b2,
                                      out, B);
}